// round 1
// baseline (speedup 1.0000x reference)
#include <cuda_runtime.h>
#include <cuda_bf16.h>
#include <math.h>
#include <stdint.h>

// Problem constants (fixed by the reference generator)
#define A_CNT   261888       // anchors per image
#define B_CNT   16           // batch
#define PRE_NMS 2000
#define POST_NMS 1000
#define NBINS   4096
#define NSORT   4096         // sort capacity (power of 2 >= candidates)
#define NPAD    2048         // padded PRE_NMS storage
#define IMG_SZ  1024.0f
#define MIN_SZ  16.0f
#define NMS_THR 0.7f

typedef unsigned long long ull;

// ---------------- device scratch (no allocations allowed) ----------------
__device__ float g_ms[B_CNT * A_CNT];            // masked scores (-inf invalid)
__device__ int   g_hist[B_CNT * NBINS];
__device__ int   g_tbin[B_CNT];
__device__ int   g_cnt[B_CNT];
__device__ int   g_cand[B_CNT * NSORT];
__device__ float4 g_boxes[B_CNT * NPAD];         // sorted top-2000 boxes (clipped)
__device__ float  g_vals[B_CNT * NPAD];          // sorted scores (-inf pad)
__device__ int    g_fcnt[B_CNT];                 // # finite entries (<=2000)
__device__ ull    g_mask[B_CNT * PRE_NMS * 32];  // NMS suppression bitmask

// ---------------- helpers ----------------
__device__ __forceinline__ void decode_clip(const float4 an, const float4 d,
                                            float& x1, float& y1, float& x2, float& y2) {
    float aw = an.z - an.x;
    float ah = an.w - an.y;
    float ax = an.x + 0.5f * aw;
    float ay = an.y + 0.5f * ah;
    float dw = fminf(d.z, 4.0f);
    float dh = fminf(d.w, 4.0f);
    float px = d.x * aw + ax;
    float py = d.y * ah + ay;
    float pw = expf(dw) * aw;
    float ph = expf(dh) * ah;
    x1 = fminf(fmaxf(px - 0.5f * pw, 0.0f), IMG_SZ);
    y1 = fminf(fmaxf(py - 0.5f * ph, 0.0f), IMG_SZ);
    x2 = fminf(fmaxf(px + 0.5f * pw, 0.0f), IMG_SZ);
    y2 = fminf(fmaxf(py + 0.5f * ph, 0.0f), IMG_SZ);
}

// ---------------- K0: zero histograms / counters ----------------
__global__ void k_init() {
    int i = blockIdx.x * blockDim.x + threadIdx.x;
    if (i < B_CNT * NBINS) g_hist[i] = 0;
    if (i < B_CNT) g_cnt[i] = 0;
}

// ---------------- K1: decode + valid mask + per-image histogram ----------------
__global__ void k_decode_hist(const float4* __restrict__ anchors,
                              const float4* __restrict__ deltas,
                              const float* __restrict__ scores) {
    const int b = blockIdx.y;
    __shared__ int sh[NBINS];
    for (int i = threadIdx.x; i < NBINS; i += blockDim.x) sh[i] = 0;
    __syncthreads();

    const int stride = gridDim.x * blockDim.x;
    for (int a = blockIdx.x * blockDim.x + threadIdx.x; a < A_CNT; a += stride) {
        float4 an = __ldg(&anchors[a]);
        float4 d  = deltas[(size_t)b * A_CNT + a];
        float x1, y1, x2, y2;
        decode_clip(an, d, x1, y1, x2, y2);
        bool valid = (x2 - x1 >= MIN_SZ) && (y2 - y1 >= MIN_SZ);
        float s = scores[(size_t)b * A_CNT + a];
        float msv = valid ? s : -INFINITY;
        g_ms[(size_t)b * A_CNT + a] = msv;
        if (valid) {
            int bin = (int)(s * (float)NBINS);
            bin = max(0, min(NBINS - 1, bin));
            atomicAdd(&sh[bin], 1);
        }
    }
    __syncthreads();
    for (int i = threadIdx.x; i < NBINS; i += blockDim.x)
        if (sh[i]) atomicAdd(&g_hist[b * NBINS + i], sh[i]);
}

// ---------------- K2: find threshold bin (suffix count >= PRE_NMS) ----------------
__global__ void k_thresh() {
    int b = threadIdx.x;
    if (b >= B_CNT) return;
    int acc = 0, t = 0;
    for (int bin = NBINS - 1; bin >= 0; --bin) {
        acc += g_hist[b * NBINS + bin];
        if (acc >= PRE_NMS) { t = bin; break; }
    }
    g_tbin[b] = t;
}

// ---------------- K3: compact candidate indices ----------------
__global__ void k_compact() {
    const int b = blockIdx.y;
    const int t = __ldg(&g_tbin[b]);
    const int stride = gridDim.x * blockDim.x;
    for (int a = blockIdx.x * blockDim.x + threadIdx.x; a < A_CNT; a += stride) {
        float v = g_ms[(size_t)b * A_CNT + a];
        if (v >= 0.0f) {  // valid scores are finite, >= 0
            int bin = (int)(v * (float)NBINS);
            bin = max(0, min(NBINS - 1, bin));
            if (bin >= t) {
                int pos = atomicAdd(&g_cnt[b], 1);
                if (pos < NSORT) g_cand[b * NSORT + pos] = a;
            }
        }
    }
}

// ---------------- K4: bitonic sort candidates, decode top-2000 ----------------
__global__ void k_sort_decode(const float4* __restrict__ anchors,
                              const float4* __restrict__ deltas,
                              const float* __restrict__ scores) {
    const int b = blockIdx.x;
    __shared__ ull sk[NSORT];  // stores ~key: ascending sort of ~key == descending by key
    const int cnt = min(g_cnt[b], NSORT);
    const int tid = threadIdx.x;

    for (int i = tid; i < NSORT; i += blockDim.x) {
        if (i < cnt) {
            int idx = g_cand[b * NSORT + i];
            float s = scores[(size_t)b * A_CNT + idx];
            unsigned ob = __float_as_uint(s);
            ob ^= (ob >> 31) ? 0xFFFFFFFFu : 0x80000000u;  // order-preserving map
            ull key = ((ull)ob << 32) | (ull)(0xFFFFFFFFu - (unsigned)idx);
            sk[i] = ~key;
        } else {
            sk[i] = ~0ull;  // pad sorts last (ascending)
        }
    }

    for (int k = 2; k <= NSORT; k <<= 1) {
        for (int j = k >> 1; j > 0; j >>= 1) {
            __syncthreads();
            for (int i = tid; i < NSORT; i += blockDim.x) {
                int ixj = i ^ j;
                if (ixj > i) {
                    ull a = sk[i], c = sk[ixj];
                    bool up = ((i & k) == 0);
                    if ((a > c) == up) { sk[i] = c; sk[ixj] = a; }
                }
            }
        }
    }
    __syncthreads();

    for (int r = tid; r < NPAD; r += blockDim.x) {
        float4 bx = make_float4(0.f, 0.f, 0.f, 0.f);
        float v = -INFINITY;
        if (r < PRE_NMS) {
            ull key = ~sk[r];
            if (key != 0ull) {
                int idx = (int)(0xFFFFFFFFu - (unsigned)(key & 0xFFFFFFFFull));
                float4 an = __ldg(&anchors[idx]);
                float4 d  = deltas[(size_t)b * A_CNT + idx];
                float x1, y1, x2, y2;
                decode_clip(an, d, x1, y1, x2, y2);
                bx = make_float4(x1, y1, x2, y2);
                v = scores[(size_t)b * A_CNT + idx];
            }
        }
        g_boxes[b * NPAD + r] = bx;
        g_vals[b * NPAD + r] = v;
    }
    if (tid == 0) g_fcnt[b] = min(cnt, PRE_NMS);
}

// ---------------- K5: NMS suppression bitmask (64x64 tiles) ----------------
__global__ void k_nms_mask() {
    const int b = blockIdx.z;
    const int cb = blockIdx.x, rb = blockIdx.y;
    const int t = threadIdx.x;
    const int r = rb * 64 + t;

    if (cb < rb) {  // strictly-lower tiles contribute nothing
        if (r < PRE_NMS) g_mask[((size_t)b * PRE_NMS + r) * 32 + cb] = 0ull;
        return;
    }

    __shared__ float4 cbox[64];
    __shared__ float carea[64];
    int c0 = cb * 64;
    float4 cx = g_boxes[b * NPAD + c0 + t];
    cbox[t] = cx;
    carea[t] = (cx.z - cx.x) * (cx.w - cx.y);
    __syncthreads();

    if (r >= PRE_NMS) return;
    float4 rbx = g_boxes[b * NPAD + r];
    float ra = (rbx.z - rbx.x) * (rbx.w - rbx.y);

    ull bits = 0ull;
    #pragma unroll 8
    for (int c = 0; c < 64; ++c) {
        int col = c0 + c;
        if (col > r) {
            float4 cc = cbox[c];
            float lx = fmaxf(rbx.x, cc.x);
            float ly = fmaxf(rbx.y, cc.y);
            float rx = fminf(rbx.z, cc.z);
            float ry = fminf(rbx.w, cc.w);
            float w = fmaxf(rx - lx, 0.0f);
            float h = fmaxf(ry - ly, 0.0f);
            float inter = w * h;
            float iou = inter / (ra + carea[c] - inter + 1e-6f);
            if (iou > NMS_THR) bits |= (1ull << c);
        }
    }
    g_mask[((size_t)b * PRE_NMS + r) * 32 + cb] = bits;
}

// ---------------- K6: sequential greedy scan + compaction + output ----------------
__global__ void k_nms_scan_out(float* __restrict__ out) {
    const int b = blockIdx.x;
    const int tid = threadIdx.x;
    const int wid = tid >> 5;
    const int lane = tid & 31;

    __shared__ ull rows[2][64][32];  // double-buffered 64 mask rows
    __shared__ ull sh_kf[32];
    __shared__ int sh_base[32];
    __shared__ int sh_tot;

    // preload rows for keep-word 0 (ranks 0..63)
    for (int e = tid; e < 2048; e += blockDim.x) {
        int i = e >> 5, j = e & 31;
        rows[0][i][j] = (i < PRE_NMS) ? g_mask[((size_t)b * PRE_NMS + i) * 32 + j] : 0ull;
    }

    ull keepw = 0ull;
    if (wid == 0) keepw = (lane < 31) ? ~0ull : 0xFFFFull;  // ranks >= 2000 excluded
    __syncthreads();

    for (int w = 0; w < 32; ++w) {
        int cur = w & 1, nxt = cur ^ 1;
        if (wid == 0) {
            // serial resolution of keep-word w from shared-resident rows
            ull vcur = __shfl_sync(0xffffffffu, keepw, w);
            ull todo = vcur;
            while (todo) {
                int p = __ffsll((long long)todo) - 1;
                todo &= todo - 1;
                ull m  = rows[cur][p][lane];   // lane's 64-col word of row p
                ull mw = rows[cur][p][w];      // broadcast: word w of row p
                keepw &= ~m;
                vcur  &= ~mw;
                todo  &= vcur;
            }
        } else if (w + 1 < 32) {
            // warps 1..7 prefetch rows for word w+1 concurrently
            for (int e = tid - 32; e < 2048; e += blockDim.x - 32) {
                int i = e >> 5, j = e & 31;
                int row = (w + 1) * 64 + i;
                rows[nxt][i][j] = (row < PRE_NMS) ? g_mask[((size_t)b * PRE_NMS + row) * 32 + j] : 0ull;
            }
        }
        __syncthreads();
    }

    // compact kept & finite entries, in rank order
    if (wid == 0) {
        int fc = g_fcnt[b];
        int nf = fc - lane * 64;
        nf = max(0, min(64, nf));
        ull fm = (nf == 64) ? ~0ull : ((nf == 0) ? 0ull : ((1ull << nf) - 1ull));
        ull kf = keepw & fm;
        int c = __popcll(kf);
        int x = c;
        for (int off = 1; off < 32; off <<= 1) {
            int y = __shfl_up_sync(0xffffffffu, x, off);
            if (lane >= off) x += y;
        }
        int base = x - c;
        sh_kf[lane] = kf;
        sh_base[lane] = base;
        if (lane == 31) sh_tot = base + c;
    }
    __syncthreads();

    const int tot = sh_tot;
    for (int r = tid; r < NPAD; r += blockDim.x) {
        int w = r >> 6, bb = r & 63;
        ull kf = sh_kf[w];
        if ((kf >> bb) & 1ull) {
            ull low = bb ? ((1ull << bb) - 1ull) : 0ull;
            int rank = sh_base[w] + __popcll(kf & low);
            if (rank < POST_NMS) {
                float4 bx = g_boxes[b * NPAD + r];
                float v = g_vals[b * NPAD + r];
                float* o = out + ((size_t)b * POST_NMS + rank) * 5;
                o[0] = bx.x; o[1] = bx.y; o[2] = bx.z; o[3] = bx.w; o[4] = v;
            }
        }
    }
    for (int r = tot + tid; r < POST_NMS; r += blockDim.x) {
        float* o = out + ((size_t)b * POST_NMS + r) * 5;
        o[0] = 0.f; o[1] = 0.f; o[2] = 0.f; o[3] = 0.f; o[4] = 0.f;
    }
}

// ---------------- launch ----------------
extern "C" void kernel_launch(void* const* d_in, const int* in_sizes, int n_in,
                              void* d_out, int out_size) {
    const float4* anchors = (const float4*)d_in[0];
    const float4* deltas  = (const float4*)d_in[1];
    const float*  scores  = (const float*)d_in[2];
    float* out = (float*)d_out;

    {
        int total = B_CNT * NBINS;
        k_init<<<(total + 255) / 256, 256>>>();
    }
    k_decode_hist<<<dim3(64, B_CNT), 256>>>(anchors, deltas, scores);
    k_thresh<<<1, 32>>>();
    k_compact<<<dim3(64, B_CNT), 256>>>();
    k_sort_decode<<<B_CNT, 1024>>>(anchors, deltas, scores);
    k_nms_mask<<<dim3(32, 32, B_CNT), 64>>>();
    k_nms_scan_out<<<B_CNT, 256>>>(out);
}